// round 1
// baseline (speedup 1.0000x reference)
#include <cuda_runtime.h>
#include <cuda_bf16.h>

#define N_NODES   100000
#define N_GRAPHS  256
#define IN_DIM    205
#define HID_DIM   128
#define FC_DIM    64
#define OUT_DIM   2

// ---------------- scratch (static device globals; no allocation) ----------------
__device__ __align__(128) float g_h1[(size_t)N_NODES * HID_DIM];    // GEMM output (both layers)
__device__ __align__(128) float g_agg[(size_t)N_NODES * HID_DIM];   // layer-1 aggregate
__device__ __align__(128) float g_agg2[(size_t)N_NODES * HID_DIM];  // layer-2 aggregate
__device__ float g_deg[N_NODES];                                    // in-degree (float)
__device__ float g_ds[N_NODES];                                     // rsqrt(deg+1)
__device__ float g_gsum[N_GRAPHS * HID_DIM];
__device__ float g_gcnt[N_GRAPHS];

// ---------------- zero the small accumulators ----------------
__global__ void zero_kernel() {
    int i = blockIdx.x * blockDim.x + threadIdx.x;
    if (i < N_NODES) g_deg[i] = 0.0f;
    if (i < N_GRAPHS * HID_DIM) g_gsum[i] = 0.0f;
    if (i < N_GRAPHS) g_gcnt[i] = 0.0f;
}

// ---------------- in-degree histogram ----------------
__global__ void deg_kernel(const int* __restrict__ dst, int E) {
    int e = blockIdx.x * blockDim.x + threadIdx.x;
    if (e < E) atomicAdd(&g_deg[dst[e]], 1.0f);
}

// ---------------- ds = rsqrt(deg+1); graph counts ----------------
__global__ void ds_kernel(const int* __restrict__ batch, int n) {
    int i = blockIdx.x * blockDim.x + threadIdx.x;
    if (i < n) {
        g_ds[i] = rsqrtf(g_deg[i] + 1.0f);
        atomicAdd(&g_gcnt[batch[i]], 1.0f);
    }
}

// ---------------- GEMM: H = in @ W  (in: [n,K], W: [K,128]) ----------------
// SECOND=false: in = X param (raw features).   Epilogue -> g_h1, g_agg  = H*ds^2
// SECOND=true : in = g_agg with relu(v + b1) applied on load. -> g_h1, g_agg2 = H*ds^2
// Block: 32 rows x 128 cols, 128 threads, each thread 8 rows x 4 cols.
template <int K, bool SECOND>
__global__ void __launch_bounds__(128) gemm_kernel(const float* __restrict__ X,
                                                   const float* __restrict__ W,
                                                   const float* __restrict__ bin) {
    __shared__ float xs[32 * K];
    const float* in = SECOND ? g_agg : X;
    float* H = g_h1;
    float* AGG = SECOND ? g_agg2 : g_agg;

    int row0 = blockIdx.x * 32;
    int tid = threadIdx.x;

    // cooperative load of 32 input rows (optionally bias+relu)
    for (int idx = tid; idx < 32 * K; idx += 128) {
        int m = idx / K;
        int k = idx - m * K;
        float v = in[(size_t)(row0 + m) * K + k];
        if (SECOND) v = fmaxf(v + bin[k], 0.0f);
        xs[idx] = v;
    }
    __syncthreads();

    int c = tid & 31;        // column group -> f0 = 4*c
    int r = tid >> 5;        // row group    -> m0 = 8*r
    int f0 = c * 4;
    int m0 = r * 8;

    float acc[8][4];
#pragma unroll
    for (int m = 0; m < 8; m++)
#pragma unroll
        for (int j = 0; j < 4; j++) acc[m][j] = 0.0f;

#pragma unroll 2
    for (int k = 0; k < K; k++) {
        float4 w = *reinterpret_cast<const float4*>(&W[k * HID_DIM + f0]);
#pragma unroll
        for (int m = 0; m < 8; m++) {
            float xv = xs[(m0 + m) * K + k];
            acc[m][0] += xv * w.x;
            acc[m][1] += xv * w.y;
            acc[m][2] += xv * w.z;
            acc[m][3] += xv * w.w;
        }
    }

#pragma unroll
    for (int m = 0; m < 8; m++) {
        int row = row0 + m0 + m;
        float dsv = g_ds[row];
        float s2 = dsv * dsv;
        float4 hv = make_float4(acc[m][0], acc[m][1], acc[m][2], acc[m][3]);
        *reinterpret_cast<float4*>(&H[(size_t)row * HID_DIM + f0]) = hv;
        float4 av = make_float4(hv.x * s2, hv.y * s2, hv.z * s2, hv.w * s2);
        *reinterpret_cast<float4*>(&AGG[(size_t)row * HID_DIM + f0]) = av;
    }
}

// ---------------- edge scatter: AGG[dst] += H[src] * ds[src]*ds[dst] ----------------
// One warp per edge; lane handles a float4 (4 features).
template <bool SECOND>
__global__ void __launch_bounds__(256) edge_kernel(const int* __restrict__ src,
                                                   const int* __restrict__ dst,
                                                   int E) {
    int gw = (blockIdx.x * blockDim.x + threadIdx.x) >> 5;
    int lane = threadIdx.x & 31;
    if (gw >= E) return;
    int s = src[gw];
    int d = dst[gw];
    float norm = g_ds[s] * g_ds[d];
    const float4 v = reinterpret_cast<const float4*>(g_h1 + (size_t)s * HID_DIM)[lane];
    float* AGG = SECOND ? g_agg2 : g_agg;
    float4* out = reinterpret_cast<float4*>(AGG + (size_t)d * HID_DIM) + lane;
    asm volatile("red.global.add.v4.f32 [%0], {%1, %2, %3, %4};"
                 :: "l"(out), "f"(v.x * norm), "f"(v.y * norm),
                    "f"(v.z * norm), "f"(v.w * norm)
                 : "memory");
}

// ---------------- layer-2 bias+relu + mean-pool accumulate ----------------
__global__ void pool_kernel(const int* __restrict__ batch,
                            const float* __restrict__ b2, int n) {
    int idx = blockIdx.x * blockDim.x + threadIdx.x;
    if (idx >= n * HID_DIM) return;
    int i = idx >> 7;
    int f = idx & 127;
    float val = fmaxf(g_agg2[idx] + b2[f], 0.0f);
    atomicAdd(&g_gsum[batch[i] * HID_DIM + f], val);
}

// ---------------- FC head: 256 blocks (one per graph) x 64 threads ----------------
__global__ void __launch_bounds__(64) fc_kernel(const float* __restrict__ Wf1,
                                                const float* __restrict__ bf1,
                                                const float* __restrict__ Wf2,
                                                const float* __restrict__ bf2,
                                                float* __restrict__ out) {
    __shared__ float grow[HID_DIM];
    __shared__ float a[FC_DIM];
    int g = blockIdx.x;
    int t = threadIdx.x;
    float inv = 1.0f / fmaxf(g_gcnt[g], 1.0f);
    grow[t] = g_gsum[g * HID_DIM + t] * inv;
    grow[t + 64] = g_gsum[g * HID_DIM + 64 + t] * inv;
    __syncthreads();
    float acc = bf1[t];
#pragma unroll 8
    for (int k = 0; k < HID_DIM; k++) acc += grow[k] * Wf1[k * FC_DIM + t];
    a[t] = fmaxf(acc, 0.0f);
    __syncthreads();
    if (t < OUT_DIM) {
        float o = bf2[t];
#pragma unroll 8
        for (int j = 0; j < FC_DIM; j++) o += a[j] * Wf2[j * OUT_DIM + t];
        out[g * OUT_DIM + t] = o;
    }
}

// ---------------- launcher ----------------
extern "C" void kernel_launch(void* const* d_in, const int* in_sizes, int n_in,
                              void* d_out, int out_size) {
    const float* x   = (const float*)d_in[0];
    const int* ei    = (const int*)d_in[1];   // [2, E] int32 (jax x64 disabled)
    const int* batch = (const int*)d_in[2];
    const float* W1  = (const float*)d_in[3];
    const float* b1  = (const float*)d_in[4];
    const float* W2  = (const float*)d_in[5];
    const float* b2  = (const float*)d_in[6];
    const float* Wf1 = (const float*)d_in[7];
    const float* bf1 = (const float*)d_in[8];
    const float* Wf2 = (const float*)d_in[9];
    const float* bf2 = (const float*)d_in[10];
    float* out = (float*)d_out;

    int E = in_sizes[1] / 2;
    int N = in_sizes[2];
    const int* src = ei;
    const int* dst = ei + E;

    zero_kernel<<<(N_NODES + 255) / 256, 256>>>();
    deg_kernel<<<(E + 255) / 256, 256>>>(dst, E);
    ds_kernel<<<(N + 255) / 256, 256>>>(batch, N);

    gemm_kernel<IN_DIM, false><<<N / 32, 128>>>(x, W1, nullptr);
    {
        long long warps = (long long)E;
        int blocks = (int)((warps * 32 + 255) / 256);
        edge_kernel<false><<<blocks, 256>>>(src, dst, E);
        gemm_kernel<HID_DIM, true><<<N / 32, 128>>>(nullptr, W2, b1);
        edge_kernel<true><<<blocks, 256>>>(src, dst, E);
    }
    pool_kernel<<<((long long)N * HID_DIM + 255) / 256, 256>>>(batch, b2, N);
    fc_kernel<<<N_GRAPHS, 64>>>(Wf1, bf1, Wf2, bf2, out);
}

// round 2
// speedup vs baseline: 1.8219x; 1.8219x over previous
#include <cuda_runtime.h>
#include <cuda_bf16.h>

#define N_NODES   100000
#define N_EDGES_MAX 1600000
#define N_GRAPHS  256
#define IN_DIM    205
#define HID_DIM   128
#define FC_DIM    64
#define OUT_DIM   2
#define SCAN_BLK  1024

// ---------------- scratch (static device globals) ----------------
__device__ __align__(128) float g_h1[(size_t)N_NODES * HID_DIM];   // hs = H*ds (both layers)
__device__ __align__(128) float g_agg[(size_t)N_NODES * HID_DIM];  // layer-1 aggregate
__device__ int   g_degi[N_NODES];
__device__ int   g_rowstart[N_NODES];
__device__ int   g_cursor[N_NODES];
__device__ int   g_blocksum[128];
__device__ int   g_csrc[N_EDGES_MAX];
__device__ float g_ds[N_NODES];
__device__ float g_gsum[N_GRAPHS * HID_DIM];
__device__ float g_gcnt[N_GRAPHS];

// ---------------- zero the small accumulators ----------------
__global__ void zero_kernel() {
    int i = blockIdx.x * blockDim.x + threadIdx.x;
    if (i < N_NODES) g_degi[i] = 0;
    if (i < N_GRAPHS * HID_DIM) g_gsum[i] = 0.0f;
    if (i < N_GRAPHS) g_gcnt[i] = 0.0f;
}

// ---------------- in-degree histogram ----------------
__global__ void hist_kernel(const int* __restrict__ dst, int E) {
    int e = blockIdx.x * blockDim.x + threadIdx.x;
    if (e < E) atomicAdd(&g_degi[dst[e]], 1);
}

// ---------------- 2-level exclusive scan ----------------
__global__ void scan1_kernel() {
    __shared__ int sh[SCAN_BLK];
    int i = blockIdx.x * SCAN_BLK + threadIdx.x;
    int v = (i < N_NODES) ? g_degi[i] : 0;
    sh[threadIdx.x] = v;
    __syncthreads();
    for (int off = 1; off < SCAN_BLK; off <<= 1) {
        int t = (threadIdx.x >= off) ? sh[threadIdx.x - off] : 0;
        __syncthreads();
        sh[threadIdx.x] += t;
        __syncthreads();
    }
    if (i < N_NODES) g_rowstart[i] = sh[threadIdx.x] - v;  // exclusive
    if (threadIdx.x == SCAN_BLK - 1) g_blocksum[blockIdx.x] = sh[threadIdx.x];
}

__global__ void scan2_kernel(int nb) {
    if (threadIdx.x == 0) {
        int acc = 0;
        for (int b = 0; b < nb; b++) { int t = g_blocksum[b]; g_blocksum[b] = acc; acc += t; }
    }
}

__global__ void scan3_kernel(const int* __restrict__ batch) {
    int i = blockIdx.x * blockDim.x + threadIdx.x;
    if (i >= N_NODES) return;
    int rs = g_rowstart[i] + g_blocksum[i / SCAN_BLK];
    g_rowstart[i] = rs;
    g_cursor[i] = rs;
    g_ds[i] = rsqrtf((float)g_degi[i] + 1.0f);
    atomicAdd(&g_gcnt[batch[i]], 1.0f);
}

// ---------------- CSR scatter (bucket order irrelevant: sum is commutative) ----------------
__global__ void scatter_kernel(const int* __restrict__ src, const int* __restrict__ dst, int E) {
    int e = blockIdx.x * blockDim.x + threadIdx.x;
    if (e < E) {
        int pos = atomicAdd(&g_cursor[dst[e]], 1);
        g_csrc[pos] = src[e];
    }
}

// ---------------- GEMM: hs = (in @ W) * ds[row]  (in: [n,K], W: [K,128]) ----------------
// SECOND=false: in = X.  SECOND=true: in = relu(g_agg + b1) on load.
// Block: 32 rows x 128 cols, 128 threads, each thread 8 rows x 4 cols, k-quad float4 LDS.
template <int K, bool SECOND>
__global__ void __launch_bounds__(128) gemm_kernel(const float* __restrict__ X,
                                                   const float* __restrict__ W,
                                                   const float* __restrict__ bin) {
    constexpr int KP = (K + 3) & ~3;
    constexpr int K4 = K & ~3;
    __shared__ float xs[32 * KP];
    const float* in = SECOND ? g_agg : X;

    int row0 = blockIdx.x * 32;
    int tid = threadIdx.x;

    for (int idx = tid; idx < 32 * K; idx += 128) {
        int m = idx / K;
        int k = idx - m * K;
        float v = in[(size_t)(row0 + m) * K + k];
        if (SECOND) v = fmaxf(v + bin[k], 0.0f);
        xs[m * KP + k] = v;
    }
    __syncthreads();

    int f0 = (tid & 31) * 4;
    int m0 = (tid >> 5) * 8;

    float acc[8][4];
#pragma unroll
    for (int m = 0; m < 8; m++)
#pragma unroll
        for (int j = 0; j < 4; j++) acc[m][j] = 0.0f;

    const float4* xs4 = reinterpret_cast<const float4*>(xs);

    for (int k = 0; k < K4; k += 4) {
        float4 w0 = *reinterpret_cast<const float4*>(&W[(k + 0) * HID_DIM + f0]);
        float4 w1 = *reinterpret_cast<const float4*>(&W[(k + 1) * HID_DIM + f0]);
        float4 w2 = *reinterpret_cast<const float4*>(&W[(k + 2) * HID_DIM + f0]);
        float4 w3 = *reinterpret_cast<const float4*>(&W[(k + 3) * HID_DIM + f0]);
#pragma unroll
        for (int m = 0; m < 8; m++) {
            float4 xv = xs4[((m0 + m) * KP + k) >> 2];
            acc[m][0] = fmaf(xv.x, w0.x, fmaf(xv.y, w1.x, fmaf(xv.z, w2.x, fmaf(xv.w, w3.x, acc[m][0]))));
            acc[m][1] = fmaf(xv.x, w0.y, fmaf(xv.y, w1.y, fmaf(xv.z, w2.y, fmaf(xv.w, w3.y, acc[m][1]))));
            acc[m][2] = fmaf(xv.x, w0.z, fmaf(xv.y, w1.z, fmaf(xv.z, w2.z, fmaf(xv.w, w3.z, acc[m][2]))));
            acc[m][3] = fmaf(xv.x, w0.w, fmaf(xv.y, w1.w, fmaf(xv.z, w2.w, fmaf(xv.w, w3.w, acc[m][3]))));
        }
    }
    // K tail (K=205 -> one scalar k)
    for (int k = K4; k < K; k++) {
        float4 w = *reinterpret_cast<const float4*>(&W[k * HID_DIM + f0]);
#pragma unroll
        for (int m = 0; m < 8; m++) {
            float xv = xs[(m0 + m) * KP + k];
            acc[m][0] = fmaf(xv, w.x, acc[m][0]);
            acc[m][1] = fmaf(xv, w.y, acc[m][1]);
            acc[m][2] = fmaf(xv, w.z, acc[m][2]);
            acc[m][3] = fmaf(xv, w.w, acc[m][3]);
        }
    }

#pragma unroll
    for (int m = 0; m < 8; m++) {
        int row = row0 + m0 + m;
        float dsv = g_ds[row];
        float4 hv = make_float4(acc[m][0] * dsv, acc[m][1] * dsv, acc[m][2] * dsv, acc[m][3] * dsv);
        *reinterpret_cast<float4*>(&g_h1[(size_t)row * HID_DIM + f0]) = hv;
    }
}

// ---------------- CSR aggregation: agg[d] = ds[d] * (sum_{e} hs[src_e] + hs[d]) ----------------
// One warp per dst node; lane owns a float4 (4 features).
// FINAL=false -> write g_agg.  FINAL=true -> relu(+b2) and RED into g_gsum[batch[d]].
template <bool FINAL>
__global__ void __launch_bounds__(256) agg_kernel(const int* __restrict__ batch,
                                                  const float* __restrict__ b2,
                                                  int n) {
    int node = (blockIdx.x * blockDim.x + threadIdx.x) >> 5;
    int lane = threadIdx.x & 31;
    if (node >= n) return;

    const float4* hs = reinterpret_cast<const float4*>(g_h1);
    float4 sum = hs[(size_t)node * 32 + lane];  // self-loop term
    int start = g_rowstart[node];
    int deg = g_degi[node];

    for (int j0 = 0; j0 < deg; j0 += 32) {
        int myid = (j0 + lane < deg) ? g_csrc[start + j0 + lane] : 0;
        int cnt = min(32, deg - j0);
#pragma unroll 4
        for (int k = 0; k < cnt; k++) {
            int s = __shfl_sync(0xffffffffu, myid, k);
            float4 v = hs[(size_t)s * 32 + lane];
            sum.x += v.x; sum.y += v.y; sum.z += v.z; sum.w += v.w;
        }
    }

    float dsv = g_ds[node];
    if (!FINAL) {
        float4 o = make_float4(sum.x * dsv, sum.y * dsv, sum.z * dsv, sum.w * dsv);
        reinterpret_cast<float4*>(g_agg)[(size_t)node * 32 + lane] = o;
    } else {
        float4 bv = reinterpret_cast<const float4*>(b2)[lane];
        float vx = fmaxf(sum.x * dsv + bv.x, 0.0f);
        float vy = fmaxf(sum.y * dsv + bv.y, 0.0f);
        float vz = fmaxf(sum.z * dsv + bv.z, 0.0f);
        float vw = fmaxf(sum.w * dsv + bv.w, 0.0f);
        float4* out = reinterpret_cast<float4*>(g_gsum) + batch[node] * 32 + lane;
        asm volatile("red.global.add.v4.f32 [%0], {%1, %2, %3, %4};"
                     :: "l"(out), "f"(vx), "f"(vy), "f"(vz), "f"(vw)
                     : "memory");
    }
}

// ---------------- FC head: 256 blocks (one per graph) x 64 threads ----------------
__global__ void __launch_bounds__(64) fc_kernel(const float* __restrict__ Wf1,
                                                const float* __restrict__ bf1,
                                                const float* __restrict__ Wf2,
                                                const float* __restrict__ bf2,
                                                float* __restrict__ out) {
    __shared__ float grow[HID_DIM];
    __shared__ float a[FC_DIM];
    int g = blockIdx.x;
    int t = threadIdx.x;
    float inv = 1.0f / fmaxf(g_gcnt[g], 1.0f);
    grow[t] = g_gsum[g * HID_DIM + t] * inv;
    grow[t + 64] = g_gsum[g * HID_DIM + 64 + t] * inv;
    __syncthreads();
    float acc = bf1[t];
#pragma unroll 8
    for (int k = 0; k < HID_DIM; k++) acc += grow[k] * Wf1[k * FC_DIM + t];
    a[t] = fmaxf(acc, 0.0f);
    __syncthreads();
    if (t < OUT_DIM) {
        float o = bf2[t];
#pragma unroll 8
        for (int j = 0; j < FC_DIM; j++) o += a[j] * Wf2[j * OUT_DIM + t];
        out[g * OUT_DIM + t] = o;
    }
}

// ---------------- launcher ----------------
extern "C" void kernel_launch(void* const* d_in, const int* in_sizes, int n_in,
                              void* d_out, int out_size) {
    const float* x   = (const float*)d_in[0];
    const int* ei    = (const int*)d_in[1];   // [2, E] int32
    const int* batch = (const int*)d_in[2];
    const float* W1  = (const float*)d_in[3];
    const float* b1  = (const float*)d_in[4];
    const float* W2  = (const float*)d_in[5];
    const float* b2  = (const float*)d_in[6];
    const float* Wf1 = (const float*)d_in[7];
    const float* bf1 = (const float*)d_in[8];
    const float* Wf2 = (const float*)d_in[9];
    const float* bf2 = (const float*)d_in[10];
    float* out = (float*)d_out;

    int E = in_sizes[1] / 2;
    int N = in_sizes[2];
    const int* src = ei;
    const int* dst = ei + E;

    int nb = (N_NODES + SCAN_BLK - 1) / SCAN_BLK;

    zero_kernel<<<(N_NODES + 255) / 256, 256>>>();
    hist_kernel<<<(E + 255) / 256, 256>>>(dst, E);
    scan1_kernel<<<nb, SCAN_BLK>>>();
    scan2_kernel<<<1, 32>>>(nb);
    scan3_kernel<<<(N_NODES + 255) / 256, 256>>>(batch);
    scatter_kernel<<<(E + 255) / 256, 256>>>(src, dst, E);

    int agg_blocks = (int)(((long long)N * 32 + 255) / 256);

    gemm_kernel<IN_DIM, false><<<N / 32, 128>>>(x, W1, nullptr);
    agg_kernel<false><<<agg_blocks, 256>>>(batch, b2, N);
    gemm_kernel<HID_DIM, true><<<N / 32, 128>>>(nullptr, W2, b1);
    agg_kernel<true><<<agg_blocks, 256>>>(batch, b2, N);

    fc_kernel<<<N_GRAPHS, 64>>>(Wf1, bf1, Wf2, bf2, out);
}

// round 3
// speedup vs baseline: 1.8666x; 1.0245x over previous
#include <cuda_runtime.h>
#include <cuda_bf16.h>

#define N_NODES   100000
#define N_EDGES_MAX 1600000
#define N_GRAPHS  256
#define IN_DIM    205
#define HID_DIM   128
#define FC_DIM    64
#define OUT_DIM   2
#define SCAN_BLK  1024

// ---------------- scratch (static device globals) ----------------
__device__ __align__(128) float g_h1[(size_t)N_NODES * HID_DIM];   // raw GEMM output H (both layers)
__device__ __align__(128) float g_agg[(size_t)N_NODES * HID_DIM];  // layer-1 aggregate (pre-bias)
__device__ int   g_degi[N_NODES];
__device__ int   g_rowstart[N_NODES];
__device__ int   g_cursor[N_NODES];
__device__ int   g_blocksum[128];
__device__ int   g_csrc[N_EDGES_MAX];
__device__ float g_ds[N_NODES];
__device__ float g_gsum[N_GRAPHS * HID_DIM];
__device__ float g_gcnt[N_GRAPHS];

// ---------------- zero the small accumulators ----------------
__global__ void zero_kernel() {
    int i = blockIdx.x * blockDim.x + threadIdx.x;
    if (i < N_NODES) g_degi[i] = 0;
    if (i < N_GRAPHS * HID_DIM) g_gsum[i] = 0.0f;
    if (i < N_GRAPHS) g_gcnt[i] = 0.0f;
}

// ---------------- in-degree histogram ----------------
__global__ void hist_kernel(const int* __restrict__ dst, int E) {
    int e = blockIdx.x * blockDim.x + threadIdx.x;
    if (e < E) atomicAdd(&g_degi[dst[e]], 1);
}

// ---------------- scan level 1: per-block exclusive scan + block sums ----------------
__global__ void scan1_kernel() {
    __shared__ int sh[SCAN_BLK];
    int i = blockIdx.x * SCAN_BLK + threadIdx.x;
    int v = (i < N_NODES) ? g_degi[i] : 0;
    sh[threadIdx.x] = v;
    __syncthreads();
    for (int off = 1; off < SCAN_BLK; off <<= 1) {
        int t = (threadIdx.x >= off) ? sh[threadIdx.x - off] : 0;
        __syncthreads();
        sh[threadIdx.x] += t;
        __syncthreads();
    }
    if (i < N_NODES) g_rowstart[i] = sh[threadIdx.x] - v;  // exclusive
    if (threadIdx.x == SCAN_BLK - 1) g_blocksum[blockIdx.x] = sh[threadIdx.x];
}

// ---------------- scan level 2 fused: each block redoes the (tiny) block-sum prefix ----------------
__global__ void scan3_kernel(const int* __restrict__ batch, int nb) {
    __shared__ int pref[128];
    int t = threadIdx.x;
    if (t == 0) {
        int acc = 0;
        for (int b = 0; b < nb; b++) { pref[b] = acc; acc += g_blocksum[b]; }
    }
    __syncthreads();
    int i = blockIdx.x * blockDim.x + t;
    if (i >= N_NODES) return;
    int rs = g_rowstart[i] + pref[i / SCAN_BLK];
    g_rowstart[i] = rs;
    g_cursor[i] = rs;
    g_ds[i] = rsqrtf((float)g_degi[i] + 1.0f);
    atomicAdd(&g_gcnt[batch[i]], 1.0f);
}

// ---------------- CSR scatter (bucket order irrelevant: sum is commutative) ----------------
__global__ void scatter_kernel(const int* __restrict__ src, const int* __restrict__ dst, int E) {
    int e = blockIdx.x * blockDim.x + threadIdx.x;
    if (e < E) {
        int pos = atomicAdd(&g_cursor[dst[e]], 1);
        g_csrc[pos] = src[e];
    }
}

// ---------------- GEMM: H = in @ W  (in: [n,K], W: [K,128]) -- NO ds dependency ----------------
// SECOND=false: in = X.  SECOND=true: in = relu(g_agg + b1) on load.
// Block: 32 rows x 128 cols, 128 threads, each thread 8 rows x 4 cols, k-quad float4 LDS.
template <int K, bool SECOND>
__global__ void __launch_bounds__(128) gemm_kernel(const float* __restrict__ X,
                                                   const float* __restrict__ W,
                                                   const float* __restrict__ bin) {
    constexpr int KP = (K + 3) & ~3;
    constexpr int K4 = K & ~3;
    __shared__ float xs[32 * KP];
    const float* in = SECOND ? g_agg : X;

    int row0 = blockIdx.x * 32;
    int tid = threadIdx.x;

    for (int idx = tid; idx < 32 * K; idx += 128) {
        int m = idx / K;
        int k = idx - m * K;
        float v = in[(size_t)(row0 + m) * K + k];
        if (SECOND) v = fmaxf(v + bin[k], 0.0f);
        xs[m * KP + k] = v;
    }
    __syncthreads();

    int f0 = (tid & 31) * 4;
    int m0 = (tid >> 5) * 8;

    float acc[8][4];
#pragma unroll
    for (int m = 0; m < 8; m++)
#pragma unroll
        for (int j = 0; j < 4; j++) acc[m][j] = 0.0f;

    const float4* xs4 = reinterpret_cast<const float4*>(xs);

    for (int k = 0; k < K4; k += 4) {
        float4 w0 = *reinterpret_cast<const float4*>(&W[(k + 0) * HID_DIM + f0]);
        float4 w1 = *reinterpret_cast<const float4*>(&W[(k + 1) * HID_DIM + f0]);
        float4 w2 = *reinterpret_cast<const float4*>(&W[(k + 2) * HID_DIM + f0]);
        float4 w3 = *reinterpret_cast<const float4*>(&W[(k + 3) * HID_DIM + f0]);
#pragma unroll
        for (int m = 0; m < 8; m++) {
            float4 xv = xs4[((m0 + m) * KP + k) >> 2];
            acc[m][0] = fmaf(xv.x, w0.x, fmaf(xv.y, w1.x, fmaf(xv.z, w2.x, fmaf(xv.w, w3.x, acc[m][0]))));
            acc[m][1] = fmaf(xv.x, w0.y, fmaf(xv.y, w1.y, fmaf(xv.z, w2.y, fmaf(xv.w, w3.y, acc[m][1]))));
            acc[m][2] = fmaf(xv.x, w0.z, fmaf(xv.y, w1.z, fmaf(xv.z, w2.z, fmaf(xv.w, w3.z, acc[m][2]))));
            acc[m][3] = fmaf(xv.x, w0.w, fmaf(xv.y, w1.w, fmaf(xv.z, w2.w, fmaf(xv.w, w3.w, acc[m][3]))));
        }
    }
    for (int k = K4; k < K; k++) {
        float4 w = *reinterpret_cast<const float4*>(&W[k * HID_DIM + f0]);
#pragma unroll
        for (int m = 0; m < 8; m++) {
            float xv = xs[(m0 + m) * KP + k];
            acc[m][0] = fmaf(xv, w.x, acc[m][0]);
            acc[m][1] = fmaf(xv, w.y, acc[m][1]);
            acc[m][2] = fmaf(xv, w.z, acc[m][2]);
            acc[m][3] = fmaf(xv, w.w, acc[m][3]);
        }
    }

#pragma unroll
    for (int m = 0; m < 8; m++) {
        int row = row0 + m0 + m;
        *reinterpret_cast<float4*>(&g_h1[(size_t)row * HID_DIM + f0]) =
            make_float4(acc[m][0], acc[m][1], acc[m][2], acc[m][3]);
    }
}

// ------- CSR aggregation: agg[d] = ds[d] * (sum_e ds[s_e]*H[s_e] + ds[d]*H[d]) -------
// One warp per dst node; lane owns a float4 (4 features). ds folded in here so the
// GEMMs have no dependency on the CSR/degree chain.
// FINAL=false -> write g_agg.  FINAL=true -> relu(+b2) and RED into g_gsum[batch[d]].
template <bool FINAL>
__global__ void __launch_bounds__(256) agg_kernel(const int* __restrict__ batch,
                                                  const float* __restrict__ b2,
                                                  int n) {
    int node = (blockIdx.x * blockDim.x + threadIdx.x) >> 5;
    int lane = threadIdx.x & 31;
    if (node >= n) return;

    const float4* __restrict__ hs = reinterpret_cast<const float4*>(g_h1);
    float dsd = g_ds[node];                     // broadcast load (same addr per warp)
    float4 self = hs[(size_t)node * 32 + lane];
    float4 sum = make_float4(dsd * self.x, dsd * self.y, dsd * self.z, dsd * self.w);

    int start = g_rowstart[node];
    int deg = g_degi[node];

    for (int j0 = 0; j0 < deg; j0 += 32) {
        int idx = j0 + lane;
        int myid = (idx < deg) ? g_csrc[start + idx] : 0;
        float myds = g_ds[myid];
        int cnt = min(32, deg - j0);
#pragma unroll 4
        for (int k = 0; k < cnt; k++) {
            int s = __shfl_sync(0xffffffffu, myid, k);
            float dss = __shfl_sync(0xffffffffu, myds, k);
            float4 v = hs[(size_t)s * 32 + lane];
            sum.x = fmaf(dss, v.x, sum.x);
            sum.y = fmaf(dss, v.y, sum.y);
            sum.z = fmaf(dss, v.z, sum.z);
            sum.w = fmaf(dss, v.w, sum.w);
        }
    }

    if (!FINAL) {
        reinterpret_cast<float4*>(g_agg)[(size_t)node * 32 + lane] =
            make_float4(sum.x * dsd, sum.y * dsd, sum.z * dsd, sum.w * dsd);
    } else {
        float4 bv = reinterpret_cast<const float4*>(b2)[lane];
        float vx = fmaxf(fmaf(sum.x, dsd, bv.x), 0.0f);
        float vy = fmaxf(fmaf(sum.y, dsd, bv.y), 0.0f);
        float vz = fmaxf(fmaf(sum.z, dsd, bv.z), 0.0f);
        float vw = fmaxf(fmaf(sum.w, dsd, bv.w), 0.0f);
        float4* out = reinterpret_cast<float4*>(g_gsum) + batch[node] * 32 + lane;
        asm volatile("red.global.add.v4.f32 [%0], {%1, %2, %3, %4};"
                     :: "l"(out), "f"(vx), "f"(vy), "f"(vz), "f"(vw)
                     : "memory");
    }
}

// ---------------- FC head: 256 blocks (one per graph) x 64 threads ----------------
__global__ void __launch_bounds__(64) fc_kernel(const float* __restrict__ Wf1,
                                                const float* __restrict__ bf1,
                                                const float* __restrict__ Wf2,
                                                const float* __restrict__ bf2,
                                                float* __restrict__ out) {
    __shared__ float grow[HID_DIM];
    __shared__ float a[FC_DIM];
    int g = blockIdx.x;
    int t = threadIdx.x;
    float inv = 1.0f / fmaxf(g_gcnt[g], 1.0f);
    grow[t] = g_gsum[g * HID_DIM + t] * inv;
    grow[t + 64] = g_gsum[g * HID_DIM + 64 + t] * inv;
    __syncthreads();
    float acc = bf1[t];
#pragma unroll 8
    for (int k = 0; k < HID_DIM; k++) acc += grow[k] * Wf1[k * FC_DIM + t];
    a[t] = fmaxf(acc, 0.0f);
    __syncthreads();
    if (t < OUT_DIM) {
        float o = bf2[t];
#pragma unroll 8
        for (int j = 0; j < FC_DIM; j++) o += a[j] * Wf2[j * OUT_DIM + t];
        out[g * OUT_DIM + t] = o;
    }
}

// ---------------- fork/join resources (created once, on the eager correctness call) ----------------
struct SideStream {
    cudaStream_t s = nullptr;
    cudaEvent_t fork = nullptr, join = nullptr;
    SideStream() {
        if (cudaStreamCreateWithFlags(&s, cudaStreamNonBlocking) != cudaSuccess) { s = nullptr; return; }
        if (cudaEventCreateWithFlags(&fork, cudaEventDisableTiming) != cudaSuccess) { s = nullptr; return; }
        if (cudaEventCreateWithFlags(&join, cudaEventDisableTiming) != cudaSuccess) { s = nullptr; return; }
    }
};
static SideStream& side() { static SideStream ss; return ss; }

// ---------------- launcher ----------------
extern "C" void kernel_launch(void* const* d_in, const int* in_sizes, int n_in,
                              void* d_out, int out_size) {
    const float* x   = (const float*)d_in[0];
    const int* ei    = (const int*)d_in[1];   // [2, E] int32
    const int* batch = (const int*)d_in[2];
    const float* W1  = (const float*)d_in[3];
    const float* b1  = (const float*)d_in[4];
    const float* W2  = (const float*)d_in[5];
    const float* b2  = (const float*)d_in[6];
    const float* Wf1 = (const float*)d_in[7];
    const float* bf1 = (const float*)d_in[8];
    const float* Wf2 = (const float*)d_in[9];
    const float* bf2 = (const float*)d_in[10];
    float* out = (float*)d_out;

    int E = in_sizes[1] / 2;
    int N = in_sizes[2];
    const int* src = ei;
    const int* dst = ei + E;
    int nb = (N_NODES + SCAN_BLK - 1) / SCAN_BLK;

    SideStream& ss = side();
    bool forked = (ss.s != nullptr);
    cudaStream_t cs = forked ? ss.s : (cudaStream_t)0;

    if (forked) {
        cudaEventRecord(ss.fork, 0);
        cudaStreamWaitEvent(ss.s, ss.fork, 0);
    }

    // --- CSR build chain (side stream): independent of GEMM1 ---
    zero_kernel<<<(N_NODES + 255) / 256, 256, 0, cs>>>();
    hist_kernel<<<(E + 255) / 256, 256, 0, cs>>>(dst, E);
    scan1_kernel<<<nb, SCAN_BLK, 0, cs>>>();
    scan3_kernel<<<(N_NODES + 255) / 256, 256, 0, cs>>>(batch, nb);
    scatter_kernel<<<(E + 255) / 256, 256, 0, cs>>>(src, dst, E);
    if (forked) cudaEventRecord(ss.join, ss.s);

    // --- GEMM1 on main stream, concurrent with CSR build ---
    gemm_kernel<IN_DIM, false><<<N / 32, 128>>>(x, W1, nullptr);

    if (forked) cudaStreamWaitEvent(0, ss.join, 0);

    int agg_blocks = (int)(((long long)N * 32 + 255) / 256);
    agg_kernel<false><<<agg_blocks, 256>>>(batch, b2, N);
    gemm_kernel<HID_DIM, true><<<N / 32, 128>>>(nullptr, W2, b1);
    agg_kernel<true><<<agg_blocks, 256>>>(batch, b2, N);

    fc_kernel<<<N_GRAPHS, 64>>>(Wf1, bf1, Wf2, bf2, out);
}